// round 7
// baseline (speedup 1.0000x reference)
#include <cuda_runtime.h>
#include <cstdint>

// Problem constants
#define NG   64                 // n
#define NN   (NG * NG)          // 4096 = N
#define SDIM (3 * NN)           // 12288, matrix dimension
#define LRF  0.001f

// One thread per g in [0, NN). Writes every nonzero of rows g, N+g, 2N+g.
// Each block redundantly computes max(c) (4096 floats, L2-resident) to get dx.
__global__ __launch_bounds__(256)
void euler_scatter_kernel(const float* __restrict__ c,
                          const float* __restrict__ kp,
                          const float* __restrict__ kx_in,
                          const float* __restrict__ ky_in,
                          const float* __restrict__ dk,
                          float* __restrict__ out)
{
    __shared__ float smax[256];
    const int tid = threadIdx.x;

    // ---- max(c) block reduction ----
    float m = -1e30f;
    for (int i = tid; i < NN; i += 256) m = fmaxf(m, c[i]);
    smax[tid] = m;
    __syncthreads();
    #pragma unroll
    for (int s = 128; s > 0; s >>= 1) {
        if (tid < s) smax[tid] = fmaxf(smax[tid], smax[tid + s]);
        __syncthreads();
    }
    // dx = DT/CN * max(c) * sqrt(2), DT=1, CN=0.1
    const float dx = (10.0f * smax[0]) * 1.41421356237309515f;

    const int r = blockIdx.x * 256 + tid;       // g index, 0..NN-1
    const int ii = r & (NG - 1);                // g % n  (within-block row)
    const int i  = r >> 6;                      // g / n  (block index)
    const int t  = ii * NG + i;                 // transpose-flatten index into row-major fields

    const bool has_pn = (r < NN - NG);          // r+n valid  <=> i < n-1  <=> t+1 same row
    const bool has_mn = (r >= NG);              // r-n valid
    const bool has_p1 = (ii != NG - 1);         // r+1 valid (within block)
    const bool has_m1 = (ii != 0);              // r-1 valid

    // ---- per-index scalars ----
    const float cf  = c[t];
    const float cd  = cf / dx;                  // cflat[r]/dx  (dy == dx)

    const float kpv  = kp[ii];
    const float minv = 1.0f / (1.0f - kpv / 2.0f);
    const float Mp   = 1.0f + kpv / 2.0f;

    const float kxr      = kx_in[t] - LRF * dk[t];
    const float nxinv_r  = 1.0f / (1.0f + kxr / 2.0f);
    const float Nxp_r    = 1.0f - kxr / 2.0f;

    const float kyr      = ky_in[t] - LRF * dk[t];
    const float nyinv_r  = 1.0f / (1.0f + kyr / 2.0f);
    const float Nyp_r    = 1.0f - kyr / 2.0f;

    // neighbors: cflat[r+n]=c[t+1], cflat[r-n]=c[t-1], cflat[r+1]=c[t+64]
    float c_pn = 0.f, c_mn = 0.f, c_p1 = 0.f;
    float nxinv_pn = 0.f, Nxp_pn = 0.f, nyinv_p1 = 0.f, Nyp_p1 = 0.f;
    if (has_pn) {
        c_pn = c[t + 1];
        const float kxp = kx_in[t + 1] - LRF * dk[t + 1];
        nxinv_pn = 1.0f / (1.0f + kxp / 2.0f);
        Nxp_pn   = 1.0f - kxp / 2.0f;
    }
    if (has_mn) c_mn = c[t - 1];
    if (has_p1) {
        c_p1 = c[t + 64];
        const float kyp = ky_in[t + 64] - LRF * dk[t + 64];
        nyinv_p1 = 1.0f / (1.0f + kyp / 2.0f);
        Nyp_p1   = 1.0f - kyp / 2.0f;
    }
    const float cpd = c_p1 / dx;                // cflat[r+1]/dy

    // ---- row r : [A11 | A12 | A13] ----
    {
        float* row = out + (size_t)r * SDIM;

        // A11 diagonal: minv*Mp + minv*((Tx@Sx)[r,r] + (Ty@Sy)[r,r])
        float txss = -cd * cd * nxinv_r;
        if (has_pn) txss += -cd * cd * nxinv_pn;
        float tyss = -cd * cd * nyinv_r;
        if (has_p1) tyss += -cpd * cpd * nyinv_p1;
        row[r] = minv * Mp + minv * (txss + tyss);

        if (has_mn) row[r - NG] = minv * cd * (c_mn / dx) * nxinv_r;     // A11[r,r-n]
        if (has_pn) row[r + NG] = minv * cd * (c_pn / dx) * nxinv_pn;    // A11[r,r+n]
        if (has_m1) row[r - 1]  = minv * cd * cd * nyinv_r;              // A11[r,r-1]
        if (has_p1) row[r + 1]  = minv * cpd * cpd * nyinv_p1;           // A11[r,r+1]

        // A12 (col offset N)
        row[NN + r] = minv * cd * nxinv_r * Nxp_r;
        if (has_pn) row[NN + r + NG] = -minv * cd * nxinv_pn * Nxp_pn;

        // A13 (col offset 2N)
        row[2 * NN + r] = minv * cd * nyinv_r * Nyp_r;
        if (has_p1) row[2 * NN + r + 1] = -minv * cpd * nyinv_p1 * Nyp_p1;
    }

    // ---- row N+r : [A21 | A22 | 0] ----
    {
        float* row = out + (size_t)(NN + r) * SDIM;
        row[r] = -nxinv_r * cd;                                          // A21 diag
        if (has_mn) row[r - NG] = nxinv_r * (c_mn / dx);                 // A21 sub (block)
        row[NN + r] = nxinv_r * Nxp_r;                                   // A22 diag
    }

    // ---- row 2N+r : [A31 | 0 | A33] ----
    {
        float* row = out + (size_t)(2 * NN + r) * SDIM;
        row[r] = -nyinv_r * cd;                                          // A31 diag
        if (has_m1) row[r - 1] = nyinv_r * cd;                           // A31 sub (within block)
        row[2 * NN + r] = nyinv_r * Nyp_r;                               // A33 diag
    }
}

extern "C" void kernel_launch(void* const* d_in, const int* in_sizes, int n_in,
                              void* d_out, int out_size)
{
    const float* c  = (const float*)d_in[0];
    const float* kp = (const float*)d_in[1];
    const float* kx = (const float*)d_in[2];
    const float* ky = (const float*)d_in[3];
    const float* dk = (const float*)d_in[4];
    float* out = (float*)d_out;

    // 1) Zero the full 3N x 3N output (604 MB) — HBM-write-bound, memset node
    //    runs at near-peak write bandwidth and is graph-capturable.
    cudaMemsetAsync(out, 0, (size_t)out_size * sizeof(float));

    // 2) Scatter the ~15*N nonzero entries. Stream order guarantees it runs
    //    after the memset inside the captured graph.
    euler_scatter_kernel<<<NN / 256, 256>>>(c, kp, kx, ky, dk, out);
}

// round 8
// speedup vs baseline: 1.0815x; 1.0815x over previous
#include <cuda_runtime.h>
#include <cstdint>

#define NG   64                 // n
#define NN   (NG * NG)          // 4096 = N
#define SDIM (3 * NN)           // 12288, matrix dimension
#define LRF  0.001f

__device__ float g_dx;

// Tiny pre-kernel: dx = 10 * max(c) * sqrt(2). Single block, 16KB read.
__global__ __launch_bounds__(256)
void max_kernel(const float* __restrict__ c)
{
    __shared__ float s[256];
    float m = 0.0f;                                  // c is uniform[0,1) -> positive
    for (int i = threadIdx.x; i < NN; i += 256) m = fmaxf(m, c[i]);
    s[threadIdx.x] = m;
    __syncthreads();
    #pragma unroll
    for (int st = 128; st > 0; st >>= 1) {
        if (threadIdx.x < st) s[threadIdx.x] = fmaxf(s[threadIdx.x], s[threadIdx.x + st]);
        __syncthreads();
    }
    if (threadIdx.x == 0) g_dx = 10.0f * s[0] * 1.41421356237309515f;
}

// Fused fill: writes all 3N x 3N elements exactly once (zeros + nonzeros).
// grid = (3, 12288), block = 256. Thread covers float4 indices
// {bx*1024 + tid + k*256 : k=0..3} of row R = blockIdx.y. Pure coalesced
// STG.128 stream; the value path triggers for ~9 threads per row only.
__global__ __launch_bounds__(256)
void fill_kernel(const float* __restrict__ c,
                 const float* __restrict__ kp,
                 const float* __restrict__ kx_in,
                 const float* __restrict__ ky_in,
                 const float* __restrict__ dk,
                 float* __restrict__ out)
{
    const int R    = blockIdx.y;
    const int base = blockIdx.x * 1024 + threadIdx.x;       // float4 index base
    float4* rowp   = (float4*)(out + (size_t)R * SDIM);

    int band, r;
    if (R < NN)          { band = 0; r = R; }
    else if (R < 2 * NN) { band = 1; r = R - NN; }
    else                 { band = 2; r = R - 2 * NN; }

    #pragma unroll
    for (int k = 0; k < 4; k++) {
        const int f4   = base + k * 256;
        const int col0 = f4 * 4;
        float4 v = make_float4(0.f, 0.f, 0.f, 0.f);

        bool hit;
        if (band == 0)
            hit = (col0 + 3 >= r - NG       && col0 <= r + NG) ||
                  (col0 + 3 >= NN + r       && col0 <= NN + r + NG) ||
                  (col0 + 3 >= 2 * NN + r   && col0 <= 2 * NN + r + 1);
        else if (band == 1)
            hit = (col0 + 3 >= r - NG       && col0 <= r) ||
                  (col0 + 3 >= NN + r       && col0 <= NN + r);
        else
            hit = (col0 + 3 >= r - 1        && col0 <= r) ||
                  (col0 + 3 >= 2 * NN + r   && col0 <= 2 * NN + r);

        if (hit) {
            // ---- value path (rare): compute this row's nonzeros, place in window ----
            const float dx = g_dx;
            const int ii = r & (NG - 1);            // g % n
            const int i  = r >> 6;                  // g / n
            const int t  = ii * NG + i;             // transpose-flatten index

            const bool has_pn = (r < NN - NG);
            const bool has_mn = (r >= NG);
            const bool has_p1 = (ii != NG - 1);
            const bool has_m1 = (ii != 0);

            const float cd = c[t] / dx;

            const float kxr     = kx_in[t] - LRF * dk[t];
            const float nxinv_r = 1.0f / (1.0f + kxr * 0.5f);
            const float Nxp_r   = 1.0f - kxr * 0.5f;

            const float kyr     = ky_in[t] - LRF * dk[t];
            const float nyinv_r = 1.0f / (1.0f + kyr * 0.5f);
            const float Nyp_r   = 1.0f - kyr * 0.5f;

            float c_pn = 0.f, c_mn = 0.f, c_p1 = 0.f;
            float nxinv_pn = 0.f, Nxp_pn = 0.f, nyinv_p1 = 0.f, Nyp_p1 = 0.f;
            if (has_pn) {
                c_pn = c[t + 1];
                const float kxp = kx_in[t + 1] - LRF * dk[t + 1];
                nxinv_pn = 1.0f / (1.0f + kxp * 0.5f);
                Nxp_pn   = 1.0f - kxp * 0.5f;
            }
            if (has_mn) c_mn = c[t - 1];
            if (has_p1) {
                c_p1 = c[t + NG];
                const float kyp = ky_in[t + NG] - LRF * dk[t + NG];
                nyinv_p1 = 1.0f / (1.0f + kyp * 0.5f);
                Nyp_p1   = 1.0f - kyp * 0.5f;
            }
            const float cpd = c_p1 / dx;

            float* vp = (float*)&v;
            #define PUT(COL, VAL) do { int _d = (COL) - col0; \
                if ((unsigned)_d < 4u) vp[_d] = (VAL); } while (0)

            if (band == 0) {
                const float kpv  = kp[ii];
                const float minv = 1.0f / (1.0f - kpv * 0.5f);
                const float Mp   = 1.0f + kpv * 0.5f;

                float txss = -cd * cd * nxinv_r;
                if (has_pn) txss += -cd * cd * nxinv_pn;
                float tyss = -cd * cd * nyinv_r;
                if (has_p1) tyss += -cpd * cpd * nyinv_p1;

                if (has_mn) PUT(r - NG, minv * cd * (c_mn / dx) * nxinv_r);
                if (has_m1) PUT(r - 1,  minv * cd * cd * nyinv_r);
                PUT(r, minv * Mp + minv * (txss + tyss));
                if (has_p1) PUT(r + 1,  minv * cpd * cpd * nyinv_p1);
                if (has_pn) PUT(r + NG, minv * cd * (c_pn / dx) * nxinv_pn);

                PUT(NN + r, minv * cd * nxinv_r * Nxp_r);
                if (has_pn) PUT(NN + r + NG, -minv * cd * nxinv_pn * Nxp_pn);

                PUT(2 * NN + r, minv * cd * nyinv_r * Nyp_r);
                if (has_p1) PUT(2 * NN + r + 1, -minv * cpd * nyinv_p1 * Nyp_p1);
            } else if (band == 1) {
                if (has_mn) PUT(r - NG, nxinv_r * (c_mn / dx));
                PUT(r, -nxinv_r * cd);
                PUT(NN + r, nxinv_r * Nxp_r);
            } else {
                if (has_m1) PUT(r - 1, nyinv_r * cd);
                PUT(r, -nyinv_r * cd);
                PUT(2 * NN + r, nyinv_r * Nyp_r);
            }
            #undef PUT
        }
        rowp[f4] = v;
    }
}

extern "C" void kernel_launch(void* const* d_in, const int* in_sizes, int n_in,
                              void* d_out, int out_size)
{
    const float* c  = (const float*)d_in[0];
    const float* kp = (const float*)d_in[1];
    const float* kx = (const float*)d_in[2];
    const float* ky = (const float*)d_in[3];
    const float* dk = (const float*)d_in[4];
    float* out = (float*)d_out;

    max_kernel<<<1, 256>>>(c);

    dim3 grid(3, SDIM);          // 3 x 12288 blocks, each block = 1024 float4 of one row
    fill_kernel<<<grid, 256>>>(c, kp, kx, ky, dk, out);
}